// round 10
// baseline (speedup 1.0000x reference)
#include <cuda_runtime.h>
#include <cstdint>

#define S_LEN 16384
#define D_DIM 256
#define V_DIM 8
#define K_HEADS 24
#define DEPTH 5          // smem ring slots per warp (DEPTH-1 rows in flight)

typedef unsigned long long u64;

__device__ __forceinline__ u64 packf2(float lo, float hi) {
    u64 r; asm("mov.b64 %0, {%1, %2};" : "=l"(r) : "f"(lo), "f"(hi)); return r;
}
__device__ __forceinline__ void unpackf2(u64 p, float& lo, float& hi) {
    asm("mov.b64 {%0, %1}, %2;" : "=f"(lo), "=f"(hi) : "l"(p));
}
// d += a*b packed f32x2 (2x fp32 FMA throughput on sm_100+)
__device__ __forceinline__ void fmaf2(u64& d, u64 a, u64 b) {
    asm("fma.rn.f32x2 %0, %1, %2, %0;" : "+l"(d) : "l"(a), "l"(b));
}
__device__ __forceinline__ u64 addf2(u64 a, u64 b) {
    u64 r; asm("add.rn.f32x2 %0, %1, %2;" : "=l"(r) : "l"(a), "l"(b)); return r;
}

__global__ __launch_bounds__(256, 2)
void attr_decoder_kernel(const float* __restrict__ feats,      // [N, 256]
                         const int*   __restrict__ mask_idx,   // [24, 16384]
                         const float* __restrict__ Wh,         // [24, 256, 8]
                         const float* __restrict__ bias,       // [24, 8]
                         float*       __restrict__ out)        // [24, 16384, 8]
{
    // Per-warp ring: 8 warps x DEPTH slots x 1KB = 40KB/CTA (2 CTAs = 80KB).
    // Row layout is chunk-interleaved: 16B chunk t (d = 4t..4t+3) lives at
    // float offset 16*(t&15) + 4*(t>>4). Then lane (q = t>>4 side) reads
    // groups of 4 chunks spanning only 64B -> conflict-free broadcast LDS.
    __shared__ __align__(16) float ring[8][DEPTH][D_DIM];

    const int k    = blockIdx.y;
    const int lane = threadIdx.x & 31;
    const int warp = threadIdx.x >> 5;
    const int s0   = blockIdx.x * 256 + warp * 32;   // 32 rows per warp
    const int q    = lane >> 3;                      // d-quarter 0..3 (64 d's)
    const int v    = lane & 7;                       // output logit owned

    // One gather index per lane covers the warp's 32 rows.
    const int idxv = mask_idx[(size_t)k * S_LEN + s0 + lane];

    const uint32_t warp_base =
        (uint32_t)__cvta_generic_to_shared(&ring[warp][0][0]);

    // Lane copies chunks t=lane and t=lane+32 (32B) into the interleaved slot.
    auto issue_row = [&](int r, int slot) {
        int i = __shfl_sync(0xffffffffu, idxv, r);
        const float* src = feats + (size_t)i * D_DIM;
        uint32_t base = warp_base + slot * (D_DIM * 4);
        int t0 = lane, t1 = lane + 32;
        uint32_t d0 = base + (16 * (t0 & 15) + 4 * (t0 >> 4)) * 4;
        uint32_t d1 = base + (16 * (t1 & 15) + 4 * (t1 >> 4)) * 4;
        asm volatile("cp.async.cg.shared.global [%0], [%1], 16;"
                     :: "r"(d0), "l"(src + 4 * t0));
        asm volatile("cp.async.cg.shared.global [%0], [%1], 16;"
                     :: "r"(d1), "l"(src + 4 * t1));
        asm volatile("cp.async.commit_group;" ::: "memory");
    };

    // ---- Prologue: DEPTH-1 rows in flight before touching weights.
    #pragma unroll
    for (int p = 0; p < DEPTH - 1; ++p) issue_row(p, p);

    // ---- Weights: lane owns d in [64q, 64q+64) for logit v, packed by d-pair.
    u64 wd[32];
    const float* wb = Wh + (size_t)k * (D_DIM * V_DIM);
    #pragma unroll
    for (int j = 0; j < 16; ++j) {
        int d0 = 64 * q + 4 * j;
        float a0 = wb[(d0 + 0) * V_DIM + v];
        float a1 = wb[(d0 + 1) * V_DIM + v];
        float a2 = wb[(d0 + 2) * V_DIM + v];
        float a3 = wb[(d0 + 3) * V_DIM + v];
        wd[2 * j + 0] = packf2(a0, a1);
        wd[2 * j + 1] = packf2(a2, a3);
    }
    const float bias_v = bias[k * V_DIM + v];

    float keepval = 0.0f;
    int rslot = 0, wslot = DEPTH - 1;

    #pragma unroll 4
    for (int r = 0; r < 32; ++r) {
        // Row r's copies (oldest) complete; DEPTH-2 newer groups may pend.
        asm volatile("cp.async.wait_group %0;" :: "n"(DEPTH - 2) : "memory");
        __syncwarp();   // cross-lane visibility + WAR guard for slot reuse

        // ---- 16 broadcast LDS (v2.b64 -> d-pairs, zero packing) + 32 fma64.
        // Lane reads d = 64q+4j+e via interleaved offset 64j + 16q bytes.
        uint32_t rb = warp_base + rslot * (D_DIM * 4) + q * 16;
        u64 acc[4] = {0ull, 0ull, 0ull, 0ull};
        #pragma unroll
        for (int j = 0; j < 16; ++j) {
            u64 f0, f1;
            asm("ld.shared.v2.b64 {%0, %1}, [%2];"
                : "=l"(f0), "=l"(f1) : "r"(rb + j * 64));
            fmaf2(acc[(2 * j) & 3], f0, wd[2 * j]);
            fmaf2(acc[(2 * j + 1) & 3], f1, wd[2 * j + 1]);
        }

        // Refill: row r+DEPTH-1 goes into the slot read LAST iteration
        // (WAR protected by this iteration's __syncwarp).
        if (r + DEPTH - 1 < 32) {
            issue_row(r + DEPTH - 1, wslot);
        } else {
            asm volatile("cp.async.commit_group;" ::: "memory");
        }

        // ---- Reduce: horizontal (in-lane) + only 2 shfl (sum 4 quarters).
        u64 s = addf2(addf2(acc[0], acc[2]), addf2(acc[1], acc[3]));
        float lo, hi;
        unpackf2(s, lo, hi);
        float h = lo + hi;                               // this lane's 64-d partial
        h += __shfl_xor_sync(0xffffffffu, h, 8);         // quarter bit 0
        h += __shfl_xor_sync(0xffffffffu, h, 16);        // quarter bit 1
        const float res = h + bias_v;                    // full dot for (row r, v)

        // Buffer 4 rows (group q keeps row rbase+q), then one coalesced
        // 128B warp store: lane (q,v) -> offset q*8+v (bijective).
        if (q == (r & 3)) keepval = res;
        if ((r & 3) == 3) {
            out[((size_t)k * S_LEN + s0 + (r - 3) + q) * V_DIM + v] = keepval;
        }

        if (++rslot == DEPTH) rslot = 0;
        if (++wslot == DEPTH) wslot = 0;
    }
}

extern "C" void kernel_launch(void* const* d_in, const int* in_sizes, int n_in,
                              void* d_out, int out_size) {
    // metadata order: block_type_grid (unused), features, mask_idx, head_weights, head_bias
    const float* feats    = (const float*)d_in[1];
    const int*   mask_idx = (const int*)  d_in[2];
    const float* Wh       = (const float*)d_in[3];
    const float* bias     = (const float*)d_in[4];
    float*       out      = (float*)d_out;

    dim3 grid(S_LEN / 256, K_HEADS);   // 64 x 24 blocks, 8 warps each, 32 rows/warp
    attr_decoder_kernel<<<grid, 256>>>(feats, mask_idx, Wh, bias, out);
}